// round 6
// baseline (speedup 1.0000x reference)
#include <cuda_runtime.h>
#include <math.h>

#define B_SZ 2
#define N_SZ 512
#define EDIM 64
#define NDIM 256
#define HEADS 8
#define DH 32
#define SCALE_F 0.17677669529663687f  // 1/sqrt(32)

// ---------------- scratch (device globals; no allocation allowed) ----------------
__device__ float g_qc[B_SZ * N_SZ * NDIM];   // nq + beq
__device__ float g_kc[B_SZ * N_SZ * NDIM];   // nk + bek
__device__ float g_vc[B_SZ * N_SZ * NDIM];   // nv + bev
__device__ float g_att[B_SZ * HEADS * N_SZ * N_SZ];  // unnormalized softmax (16MB)
__device__ float g_ce[B_SZ * N_SZ * HEADS * EDIM];   // ctx_e per (b,i,h,64)
__device__ float g_ssum[B_SZ * N_SZ * HEADS];        // softmax denominators

// ---------------- helpers ----------------
__device__ __forceinline__ unsigned f2tf(float f) {
    unsigned u; asm("cvt.rna.tf32.f32 %0, %1;" : "=r"(u) : "f"(f)); return u;
}
__device__ __forceinline__ void mma_tf32(float* d, const unsigned* a, const unsigned* b) {
    asm("mma.sync.aligned.m16n8k8.row.col.f32.tf32.tf32.f32 "
        "{%0,%1,%2,%3}, {%4,%5,%6,%7}, {%8,%9}, {%0,%1,%2,%3};"
        : "+f"(d[0]), "+f"(d[1]), "+f"(d[2]), "+f"(d[3])
        : "r"(a[0]), "r"(a[1]), "r"(a[2]), "r"(a[3]), "r"(b[0]), "r"(b[1]));
}
__device__ __forceinline__ void cp_async16(void* smem_dst, const void* gsrc) {
    unsigned s = (unsigned)__cvta_generic_to_shared(smem_dst);
    asm volatile("cp.async.cg.shared.global [%0], [%1], 16;" :: "r"(s), "l"(gsrc));
}

// =================================================================================
// Kernel A: node projections (proven).
// =================================================================================
__global__ __launch_bounds__(256) void node_proj_kernel(
    const float* __restrict__ node,
    const float* __restrict__ Wnq, const float* __restrict__ bnq,
    const float* __restrict__ Wnk, const float* __restrict__ bnk,
    const float* __restrict__ Wnv, const float* __restrict__ bnv,
    const float* __restrict__ beq, const float* __restrict__ bek,
    const float* __restrict__ bev)
{
    extern __shared__ float smA[];
    float* node_s = smA;             // 8*257
    float* wt     = smA + 8 * 257;   // 64*260

    const int tid = threadIdx.x;
    const int r  = tid & 7;
    const int cg = tid >> 3;
    const int r0 = blockIdx.x * 8;
    const int p  = blockIdx.y;

    const float* W  = (p == 0) ? Wnq : (p == 1) ? Wnk : Wnv;
    const float* b1 = (p == 0) ? bnq : (p == 1) ? bnk : bnv;
    const float* b2 = (p == 0) ? beq : (p == 1) ? bek : bev;
    float* dst = (p == 0) ? g_qc : (p == 1) ? g_kc : g_vc;

    for (int idx = tid; idx < 8 * 256; idx += 256) {
        int rr = idx >> 8, k = idx & 255;
        node_s[rr * 257 + k] = node[(r0 + rr) * 256 + k];
    }

    float acc[8];
    #pragma unroll
    for (int q = 0; q < 8; q++) acc[q] = 0.f;

    for (int kt = 0; kt < 4; kt++) {
        __syncthreads();
        for (int idx = tid; idx < 64 * 256; idx += 256) {
            int c = idx >> 6, kk = idx & 63;
            wt[kk * 260 + c] = W[c * 256 + kt * 64 + kk];
        }
        __syncthreads();
        #pragma unroll 4
        for (int kk = 0; kk < 64; kk++) {
            float nv = node_s[r * 257 + kt * 64 + kk];
            const float* wrow = &wt[kk * 260 + cg * 8];
            float4 w0 = *(const float4*)(wrow);
            float4 w1 = *(const float4*)(wrow + 4);
            acc[0] += w0.x * nv; acc[1] += w0.y * nv; acc[2] += w0.z * nv; acc[3] += w0.w * nv;
            acc[4] += w1.x * nv; acc[5] += w1.y * nv; acc[6] += w1.z * nv; acc[7] += w1.w * nv;
        }
    }
    int row = r0 + r;
    #pragma unroll
    for (int q4 = 0; q4 < 2; q4++) {
        float4 bb1 = *(const float4*)&b1[cg * 8 + q4 * 4];
        float4 bb2 = *(const float4*)&b2[cg * 8 + q4 * 4];
        float4 v;
        v.x = acc[q4 * 4 + 0] + bb1.x + bb2.x;
        v.y = acc[q4 * 4 + 1] + bb1.y + bb2.y;
        v.z = acc[q4 * 4 + 2] + bb1.z + bb2.z;
        v.w = acc[q4 * 4 + 3] + bb1.w + bb2.w;
        *(float4*)&dst[row * 256 + cg * 8 + q4 * 4] = v;
    }
}

// =================================================================================
// Kernel B: per (b,i) CTA, 512 threads. warp = (head h, j-slice s).
// Phase 1: 16 tiles of 32 j; each warp does a m16n32k64 pair of GEMM fragments
// with fragment-order weights in smem (1 LDS.64 per mma B-operand) and kc
// register-prefetched. ~32 accum regs/thread -> no spills.
// Softmax -> g_att (tf32-rounded). Phase 2: ctx_e = att @ E via mma.
// =================================================================================
__global__ __launch_bounds__(512) void attn_kernel(
    const float* __restrict__ edge,
    const float* __restrict__ Weq, const float* __restrict__ Wek)
{
    extern __shared__ float sm[];
    float* sWfq = sm;            // 16384: [h][ni][k][lane][2] fragment order
    float* sWfk = sm + 16384;    // 16384
    float* sE1  = sm + 32768;    // 3 x 2176 (32j x 68) phase-1 tile ring
    float* sQK  = sm + 39296;    // 8 x 516
    float* sQC  = sm + 43424;    // 256
    float* sMax = sm + 43680;    // 16
    float* sSum = sm + 43696;    // 16
    float* sCE  = sm + 43712;    // 1024
    // total 44736 floats = 178944 B.  Phase 2 aliases sm[0..17408) as 256x68 tile.

    const int i = blockIdx.x;
    const int b = blockIdx.y;
    const int tid = threadIdx.x;
    const int lane = tid & 31;
    const int wid = tid >> 5;
    const int h = wid & 7;
    const int s = wid >> 3;
    const int g = lane >> 2;
    const int c = lane & 3;

    const int bN = b * N_SZ;
    const float* edgeRowBase = edge + (size_t)(bN + i) * N_SZ * EDIM;

    // ---- start cp.async of tile 0 (one float4 per thread) ----
    {
        const float4* src = (const float4*)(edgeRowBase);
        int row = tid >> 4, q = tid & 15;
        cp_async16(sE1 + row * 68 + q * 4, src + tid);
        asm volatile("cp.async.commit_group;");
    }

    // ---- build fragment-order tf32 weights in smem ----
    // entry idx over (hh,ni,k,l) = 8*4*8*32 = 8192; each entry holds 2 floats.
    for (int idx = tid; idx < 8192; idx += 512) {
        int l  = idx & 31;
        int k  = (idx >> 5) & 7;
        int ni = (idx >> 8) & 3;
        int hh = idx >> 10;
        int gg = l >> 2, cc = l & 3;
        int wrow = hh * 32 + ni * 8 + gg;
        unsigned* dq = (unsigned*)&sWfq[idx * 2];
        unsigned* dk = (unsigned*)&sWfk[idx * 2];
        dq[0] = f2tf(__ldg(&Weq[wrow * 64 + k * 8 + cc]));
        dq[1] = f2tf(__ldg(&Weq[wrow * 64 + k * 8 + cc + 4]));
        dk[0] = f2tf(__ldg(&Wek[wrow * 64 + k * 8 + cc]));
        dk[1] = f2tf(__ldg(&Wek[wrow * 64 + k * 8 + cc + 4]));
    }
    if (tid < 256) sQC[tid] = g_qc[(bN + i) * NDIM + tid];

    // ---------------- Phase 1 ----------------
    for (int jt = 0; jt < 16; jt++) {
        if (jt < 15) {
            const float4* src = (const float4*)(edgeRowBase + (jt + 1) * 32 * EDIM);
            float* dstb = sE1 + ((jt + 1) % 3) * 2176;
            int row = tid >> 4, q = tid & 15;
            cp_async16(dstb + row * 68 + q * 4, src + tid);
            asm volatile("cp.async.commit_group;");
            asm volatile("cp.async.wait_group 1;");
        } else {
            asm volatile("cp.async.wait_group 0;");
        }
        __syncthreads();

        const unsigned* eb = (const unsigned*)(sE1 + (jt % 3) * 2176);
        const int jg0 = jt * 32;
        const int r0 = s * 16 + g;

        // prefetch kc for this warp's 16 rows (overlaps with mma below)
        float2 kr[4][2];
        #pragma unroll
        for (int ni = 0; ni < 4; ni++) {
            int ch = h * 32 + ni * 8 + 2 * c;
            kr[ni][0] = __ldg((const float2*)(g_kc + (size_t)(bN + jg0 + r0) * NDIM + ch));
            kr[ni][1] = __ldg((const float2*)(g_kc + (size_t)(bN + jg0 + r0 + 8) * NDIM + ch));
        }

        float Dq[4][4], Dk[4][4];
        #pragma unroll
        for (int ni = 0; ni < 4; ni++)
            #pragma unroll
            for (int e = 0; e < 4; e++) { Dq[ni][e] = 0.f; Dk[ni][e] = 0.f; }

        #pragma unroll
        for (int k = 0; k < 8; k++) {
            unsigned a[4];
            a[0] = eb[r0 * 68 + k * 8 + c];
            a[1] = eb[(r0 + 8) * 68 + k * 8 + c];
            a[2] = eb[r0 * 68 + k * 8 + c + 4];
            a[3] = eb[(r0 + 8) * 68 + k * 8 + c + 4];
            #pragma unroll
            for (int ni = 0; ni < 4; ni++) {
                const int wi = (((h * 4 + ni) * 8 + k) * 32 + lane) * 2;
                uint2 bq = *(const uint2*)&sWfq[wi];
                uint2 bk = *(const uint2*)&sWfk[wi];
                mma_tf32(Dq[ni], a, (const unsigned*)&bq);
                mma_tf32(Dk[ni], a, (const unsigned*)&bk);
            }
        }

        // combine: qk[j] = sum_d (EQ+qc)(EK+kc)
        float accA = 0.f, accB = 0.f;
        #pragma unroll
        for (int ni = 0; ni < 4; ni++) {
            int ch = h * 32 + ni * 8 + 2 * c;
            float q0 = sQC[ch], q1 = sQC[ch + 1];
            accA += (Dq[ni][0] + q0) * (Dk[ni][0] + kr[ni][0].x)
                  + (Dq[ni][1] + q1) * (Dk[ni][1] + kr[ni][0].y);
            accB += (Dq[ni][2] + q0) * (Dk[ni][2] + kr[ni][1].x)
                  + (Dq[ni][3] + q1) * (Dk[ni][3] + kr[ni][1].y);
        }
        #pragma unroll
        for (int t = 1; t <= 2; t <<= 1) {
            accA += __shfl_xor_sync(0xffffffffu, accA, t);
            accB += __shfl_xor_sync(0xffffffffu, accB, t);
        }
        if (c == 0) {
            sQK[h * 516 + jg0 + r0]     = accA * SCALE_F;
            sQK[h * 516 + jg0 + r0 + 8] = accB * SCALE_F;
        }
    }
    __syncthreads();

    // ---------------- Softmax: warp (s,h) handles half-row; att -> rna tf32 -------
    float* srow = sQK + h * 516;
    {
        float m = -1e30f;
        for (int jj = s * 256 + lane; jj < s * 256 + 256; jj += 32)
            m = fmaxf(m, srow[jj]);
        #pragma unroll
        for (int off = 16; off > 0; off >>= 1) m = fmaxf(m, __shfl_xor_sync(0xffffffffu, m, off));
        if (lane == 0) sMax[s * 8 + h] = m;
    }
    __syncthreads();
    {
        float M = fmaxf(sMax[h], sMax[8 + h]);
        float ssum = 0.f;
        float* gatt = g_att + ((size_t)(b * HEADS + h) * N_SZ + i) * N_SZ;
        for (int jj = s * 256 + lane; jj < s * 256 + 256; jj += 32) {
            float p = __expf(srow[jj] - M);
            float pr = __uint_as_float(f2tf(p));  // tf32-representable: exact in mma
            srow[jj] = pr;
            gatt[jj] = pr;
            ssum += pr;
        }
        #pragma unroll
        for (int off = 16; off > 0; off >>= 1) ssum += __shfl_xor_sync(0xffffffffu, ssum, off);
        if (lane == 0) sSum[s * 8 + h] = ssum;
    }

    // ---------------- Phase 2: ctx_e = att @ E via mma ---------------------------
    const int nt = wid & 7;    // 8-col d-slice
    const int sub = wid >> 3;  // j-half within pass
    float Dc[4] = {0.f, 0.f, 0.f, 0.f};
    float* sE2 = sm;  // 256 x 68 = 17408 floats, aliases weight region

    for (int pass = 0; pass < 2; pass++) {
        __syncthreads();
        if (pass == 0 && tid < 8)
            g_ssum[(size_t)(bN + i) * HEADS + tid] = sSum[tid] + sSum[8 + tid];
        {   // stage 256 x 64 edge rows (stride 68)
            const float4* src = (const float4*)(edgeRowBase + (size_t)pass * 256 * EDIM);
            #pragma unroll
            for (int u = 0; u < 8; u++) {
                int idx = tid + u * 512;
                int row = idx >> 4, q = idx & 15;
                cp_async16(sE2 + row * 68 + q * 4, src + idx);
            }
            asm volatile("cp.async.commit_group;");
            asm volatile("cp.async.wait_group 0;");
        }
        __syncthreads();

        #pragma unroll
        for (int cc = 0; cc < 16; cc++) {
            const int jl = sub * 128 + cc * 8;           // within pass
            const int jg = pass * 256 + jl;              // global j
            unsigned aa[4], bb[2];
            aa[0] = (g < 8) ? __float_as_uint(sQK[g * 516 + jg + c]) : 0u;
            aa[1] = 0u;
            aa[2] = (g < 8) ? __float_as_uint(sQK[g * 516 + jg + c + 4]) : 0u;
            aa[3] = 0u;
            bb[0] = __float_as_uint(sE2[(jl + c) * 68 + nt * 8 + g]);
            bb[1] = __float_as_uint(sE2[(jl + c + 4) * 68 + nt * 8 + g]);
            mma_tf32(Dc, aa, bb);
        }
    }
    // lane (g,c) holds D[head g][nt*8 + 2c, 2c+1]  (g<8)
    if (g < 8) {
        sCE[sub * 512 + g * 64 + nt * 8 + 2 * c]     = Dc[0];
        sCE[sub * 512 + g * 64 + nt * 8 + 2 * c + 1] = Dc[1];
    }
    __syncthreads();
    g_ce[(size_t)(bN + i) * 512 + tid] = sCE[tid] + sCE[512 + tid];
}

// =================================================================================
// Kernel C: out = ( Wev·ctx_e + att@vc ) / ssum.  CTA = (it, h, b), 256 threads.
// =================================================================================
__global__ __launch_bounds__(256) void out_kernel(
    const float* __restrict__ Wev,
    float* __restrict__ out)
{
    extern __shared__ float smC[];
    float* svc  = smC;               // 512 x 32
    float* sWev = smC + 16384;       // 32 x 65
    float* sCe  = smC + 18464;       // 64 x 64
    // total 22560 floats

    const int it = blockIdx.x;
    const int h  = blockIdx.y;
    const int b  = blockIdx.z;
    const int tid = threadIdx.x;
    const int ti = tid >> 5;
    const int lane = tid & 31;

    for (int idx = tid; idx < 512 * 8; idx += 256) {
        int j = idx >> 3, q = idx & 7;
        float4 v = __ldg((const float4*)&g_vc[(size_t)(b * N_SZ + j) * NDIM + h * 32 + q * 4]);
        *(float4*)&svc[j * 32 + q * 4] = v;
    }
    for (int idx = tid; idx < 2048; idx += 256) {
        int row = idx >> 6, dp = idx & 63;
        sWev[row * 65 + dp] = __ldg(&Wev[(h * 32 + row) * 64 + dp]);
    }
    for (int idx = tid; idx < 64 * 16; idx += 256) {
        int il = idx >> 4, q = idx & 15;
        float4 v = __ldg((const float4*)&g_ce[(size_t)(b * N_SZ + it * 64 + il) * 512 + h * 64 + q * 4]);
        *(float4*)&sCe[il * 64 + q * 4] = v;
    }
    __syncthreads();

    for (int iq = 0; iq < 2; iq++) {
        const int i0 = iq * 32 + ti * 4;
        const float* arow = g_att + ((size_t)(b * HEADS + h) * N_SZ + it * 64 + i0) * N_SZ;
        float acc0 = 0.f, acc1 = 0.f, acc2 = 0.f, acc3 = 0.f;
        #pragma unroll 4
        for (int j = 0; j < 512; j += 4) {
            float4 a0 = __ldg((const float4*)(arow + j));
            float4 a1 = __ldg((const float4*)(arow + 512 + j));
            float4 a2 = __ldg((const float4*)(arow + 1024 + j));
            float4 a3 = __ldg((const float4*)(arow + 1536 + j));
            float v0 = svc[(j + 0) * 32 + lane];
            float v1 = svc[(j + 1) * 32 + lane];
            float v2 = svc[(j + 2) * 32 + lane];
            float v3 = svc[(j + 3) * 32 + lane];
            acc0 += a0.x * v0 + a0.y * v1 + a0.z * v2 + a0.w * v3;
            acc1 += a1.x * v0 + a1.y * v1 + a1.z * v2 + a1.w * v3;
            acc2 += a2.x * v0 + a2.y * v1 + a2.z * v2 + a2.w * v3;
            acc3 += a3.x * v0 + a3.y * v1 + a3.z * v2 + a3.w * v3;
        }
        float accs[4] = {acc0, acc1, acc2, acc3};
        #pragma unroll
        for (int ii = 0; ii < 4; ii++) {
            int il = i0 + ii;
            float dot = 0.f;
            #pragma unroll 8
            for (int dp = 0; dp < 64; dp++)
                dot += sCe[il * 64 + dp] * sWev[lane * 65 + dp];
            int ig = it * 64 + il;
            float inv = 1.f / __ldg(&g_ssum[(size_t)(b * N_SZ + ig) * HEADS + h]);
            out[(size_t)(b * N_SZ + ig) * NDIM + h * 32 + lane] = (dot + accs[ii]) * inv;
        }
    }
}

// =================================================================================
extern "C" void kernel_launch(void* const* d_in, const int* in_sizes, int n_in,
                              void* d_out, int out_size)
{
    const float* node = (const float*)d_in[0];
    const float* edge = (const float*)d_in[1];
    const float* Wnq  = (const float*)d_in[2];
    const float* bnq  = (const float*)d_in[3];
    const float* Wnk  = (const float*)d_in[4];
    const float* bnk  = (const float*)d_in[5];
    const float* Wnv  = (const float*)d_in[6];
    const float* bnv  = (const float*)d_in[7];
    const float* Weq  = (const float*)d_in[8];
    const float* beq  = (const float*)d_in[9];
    const float* Wek  = (const float*)d_in[10];
    const float* bek  = (const float*)d_in[11];
    const float* Wev  = (const float*)d_in[12];
    const float* bev  = (const float*)d_in[13];
    float* out = (float*)d_out;

    const int smemA = (8 * 257 + 64 * 260) * 4;      // 74784 B
    const int smemB = 44736 * 4;                     // 178944 B
    const int smemC = 22560 * 4;                     // 90240 B
    cudaFuncSetAttribute(node_proj_kernel, cudaFuncAttributeMaxDynamicSharedMemorySize, smemA);
    cudaFuncSetAttribute(attn_kernel, cudaFuncAttributeMaxDynamicSharedMemorySize, smemB);
    cudaFuncSetAttribute(out_kernel, cudaFuncAttributeMaxDynamicSharedMemorySize, smemC);

    dim3 gridA(128, 3);
    node_proj_kernel<<<gridA, 256, smemA>>>(node, Wnq, bnq, Wnk, bnk, Wnv, bnv, beq, bek, bev);

    dim3 gridB(N_SZ, B_SZ);
    attn_kernel<<<gridB, 512, smemB>>>(edge, Weq, Wek);

    dim3 gridC(8, HEADS, B_SZ);
    out_kernel<<<gridC, 256, smemC>>>(Wev, out);
}

// round 7
// speedup vs baseline: 1.1937x; 1.1937x over previous
#include <cuda_runtime.h>
#include <math.h>

#define B_SZ 2
#define N_SZ 512
#define EDIM 64
#define NDIM 256
#define HEADS 8
#define DH 32
#define SCALE_F 0.17677669529663687f  // 1/sqrt(32)

// ---------------- scratch (device globals; no allocation allowed) ----------------
__device__ float g_qc[B_SZ * N_SZ * NDIM];   // nq + beq
__device__ float g_kc[B_SZ * N_SZ * NDIM];   // nk + bek
__device__ float g_vc[B_SZ * N_SZ * NDIM];   // nv + bev
__device__ float g_att[B_SZ * HEADS * N_SZ * N_SZ];  // unnormalized softmax (16MB)
__device__ float g_ce[B_SZ * N_SZ * HEADS * EDIM];   // ctx_e per (b,i,h,64)
__device__ float g_ssum[B_SZ * N_SZ * HEADS];        // softmax denominators
__device__ float g_wfq[16384];  // fragment-ordered tf32 Weq  [h][ni][k][lane][2]
__device__ float g_wfk[16384];  // fragment-ordered tf32 Wek

// ---------------- helpers ----------------
__device__ __forceinline__ unsigned f2tf(float f) {
    unsigned u; asm("cvt.rna.tf32.f32 %0, %1;" : "=r"(u) : "f"(f)); return u;
}
__device__ __forceinline__ void mma_tf32(float* d, const unsigned* a, const unsigned* b) {
    asm("mma.sync.aligned.m16n8k8.row.col.f32.tf32.tf32.f32 "
        "{%0,%1,%2,%3}, {%4,%5,%6,%7}, {%8,%9}, {%0,%1,%2,%3};"
        : "+f"(d[0]), "+f"(d[1]), "+f"(d[2]), "+f"(d[3])
        : "r"(a[0]), "r"(a[1]), "r"(a[2]), "r"(a[3]), "r"(b[0]), "r"(b[1]));
}
__device__ __forceinline__ void cp_async16(void* smem_dst, const void* gsrc) {
    unsigned s = (unsigned)__cvta_generic_to_shared(smem_dst);
    asm volatile("cp.async.cg.shared.global [%0], [%1], 16;" :: "r"(s), "l"(gsrc));
}

// =================================================================================
// Kernel W: build fragment-ordered tf32 weight tables in global memory.
// =================================================================================
__global__ __launch_bounds__(256) void weight_frag_kernel(
    const float* __restrict__ Weq, const float* __restrict__ Wek)
{
    int idx = blockIdx.x * 256 + threadIdx.x;   // 0..8191
    if (idx >= 8192) return;
    int l  = idx & 31;
    int k  = (idx >> 5) & 7;
    int ni = (idx >> 8) & 3;
    int hh = idx >> 10;
    int gg = l >> 2, cc = l & 3;
    int wrow = hh * 32 + ni * 8 + gg;
    unsigned* dq = (unsigned*)&g_wfq[idx * 2];
    unsigned* dk = (unsigned*)&g_wfk[idx * 2];
    dq[0] = f2tf(Weq[wrow * 64 + k * 8 + cc]);
    dq[1] = f2tf(Weq[wrow * 64 + k * 8 + cc + 4]);
    dk[0] = f2tf(Wek[wrow * 64 + k * 8 + cc]);
    dk[1] = f2tf(Wek[wrow * 64 + k * 8 + cc + 4]);
}

// =================================================================================
// Kernel A: node projections. grid (64, 3), 16 rows/CTA.
// =================================================================================
__global__ __launch_bounds__(256) void node_proj_kernel(
    const float* __restrict__ node,
    const float* __restrict__ Wnq, const float* __restrict__ bnq,
    const float* __restrict__ Wnk, const float* __restrict__ bnk,
    const float* __restrict__ Wnv, const float* __restrict__ bnv,
    const float* __restrict__ beq, const float* __restrict__ bek,
    const float* __restrict__ bev)
{
    extern __shared__ float smA[];
    float* node_s = smA;              // 16*257 = 4112
    float* wt     = smA + 16 * 257;   // 64*260 = 16640

    const int tid = threadIdx.x;
    const int r  = tid & 15;
    const int cg = tid >> 4;
    const int r0 = blockIdx.x * 16;
    const int p  = blockIdx.y;

    const float* W  = (p == 0) ? Wnq : (p == 1) ? Wnk : Wnv;
    const float* b1 = (p == 0) ? bnq : (p == 1) ? bnk : bnv;
    const float* b2 = (p == 0) ? beq : (p == 1) ? bek : bev;
    float* dst = (p == 0) ? g_qc : (p == 1) ? g_kc : g_vc;

    for (int idx = tid; idx < 16 * 256; idx += 256) {
        int rr = idx >> 8, k = idx & 255;
        node_s[rr * 257 + k] = node[(r0 + rr) * 256 + k];
    }

    float acc[16];
    #pragma unroll
    for (int q = 0; q < 16; q++) acc[q] = 0.f;

    for (int kt = 0; kt < 4; kt++) {
        __syncthreads();
        for (int idx = tid; idx < 64 * 256; idx += 256) {
            int c = idx >> 6, kk = idx & 63;
            wt[kk * 260 + c] = W[c * 256 + kt * 64 + kk];
        }
        __syncthreads();
        #pragma unroll 4
        for (int kk = 0; kk < 64; kk++) {
            float nv = node_s[r * 257 + kt * 64 + kk];
            const float* wrow = &wt[kk * 260 + cg * 16];
            float4 w0 = *(const float4*)(wrow);
            float4 w1 = *(const float4*)(wrow + 4);
            float4 w2 = *(const float4*)(wrow + 8);
            float4 w3 = *(const float4*)(wrow + 12);
            acc[0]  += w0.x * nv; acc[1]  += w0.y * nv; acc[2]  += w0.z * nv; acc[3]  += w0.w * nv;
            acc[4]  += w1.x * nv; acc[5]  += w1.y * nv; acc[6]  += w1.z * nv; acc[7]  += w1.w * nv;
            acc[8]  += w2.x * nv; acc[9]  += w2.y * nv; acc[10] += w2.z * nv; acc[11] += w2.w * nv;
            acc[12] += w3.x * nv; acc[13] += w3.y * nv; acc[14] += w3.z * nv; acc[15] += w3.w * nv;
        }
    }
    int row = r0 + r;
    #pragma unroll
    for (int q4 = 0; q4 < 4; q4++) {
        float4 bb1 = *(const float4*)&b1[cg * 16 + q4 * 4];
        float4 bb2 = *(const float4*)&b2[cg * 16 + q4 * 4];
        float4 v;
        v.x = acc[q4 * 4 + 0] + bb1.x + bb2.x;
        v.y = acc[q4 * 4 + 1] + bb1.y + bb2.y;
        v.z = acc[q4 * 4 + 2] + bb1.z + bb2.z;
        v.w = acc[q4 * 4 + 3] + bb1.w + bb2.w;
        *(float4*)&dst[row * 256 + cg * 16 + q4 * 4] = v;
    }
}

// =================================================================================
// Kernel B: per (b,i) CTA, 256 threads = 8 warps (warp = head). 89KB smem ->
// 2 CTAs/SM. Phase 1: 16 tiles of 32 j, m32n32k64 per warp; B-fragments from
// L1-resident global tables (no weight smem, no weight regs).
// =================================================================================
__global__ __launch_bounds__(256, 2) void attn_kernel(
    const float* __restrict__ edge)
{
    extern __shared__ float sm[];
    float* sQK = sm;             // 8 x 516 = 4128
    float* sQC = sm + 4128;      // 256
    float* sCE = sm + 4384;      // 512
    float* sE  = sm + 4896;      // phase1: 3 x 2176 ring; phase2: 256 x 68 = 17408
    // total 22304 floats = 89216 bytes

    const int i = blockIdx.x;
    const int b = blockIdx.y;
    const int tid = threadIdx.x;
    const int lane = tid & 31;
    const int h = tid >> 5;      // warp = head
    const int g = lane >> 2;
    const int c = lane & 3;

    const int bN = b * N_SZ;
    const float* edgeRowBase = edge + (size_t)(bN + i) * N_SZ * EDIM;

    // ---- start cp.async of tile 0 (2 float4 per thread) ----
    {
        const float4* src = (const float4*)(edgeRowBase);
        #pragma unroll
        for (int u = 0; u < 2; u++) {
            int idx = tid + u * 256;
            int row = idx >> 4, q = idx & 15;
            cp_async16(sE + row * 68 + q * 4, src + idx);
        }
        asm volatile("cp.async.commit_group;");
    }
    sQC[tid] = g_qc[(bN + i) * NDIM + tid];

    // ---------------- Phase 1: 16 tiles of 32 j ----------------
    for (int jt = 0; jt < 16; jt++) {
        if (jt < 15) {
            const float4* src = (const float4*)(edgeRowBase + (jt + 1) * 32 * EDIM);
            float* dstb = sE + ((jt + 1) % 3) * 2176;
            #pragma unroll
            for (int u = 0; u < 2; u++) {
                int idx = tid + u * 256;
                int row = idx >> 4, q = idx & 15;
                cp_async16(dstb + row * 68 + q * 4, src + idx);
            }
            asm volatile("cp.async.commit_group;");
            asm volatile("cp.async.wait_group 1;");
        } else {
            asm volatile("cp.async.wait_group 0;");
        }
        __syncthreads();

        const unsigned* eb = (const unsigned*)(sE + (jt % 3) * 2176);
        const int jg0 = jt * 32;

        float Dq[2][4][4], Dk[2][4][4];
        #pragma unroll
        for (int mi = 0; mi < 2; mi++)
            #pragma unroll
            for (int ni = 0; ni < 4; ni++)
                #pragma unroll
                for (int e = 0; e < 4; e++) { Dq[mi][ni][e] = 0.f; Dk[mi][ni][e] = 0.f; }

        #pragma unroll
        for (int k = 0; k < 8; k++) {
            unsigned a0[4], a1[4];
            a0[0] = eb[g * 68 + k * 8 + c];            a0[1] = eb[(g + 8) * 68 + k * 8 + c];
            a0[2] = eb[g * 68 + k * 8 + c + 4];        a0[3] = eb[(g + 8) * 68 + k * 8 + c + 4];
            a1[0] = eb[(16 + g) * 68 + k * 8 + c];     a1[1] = eb[(24 + g) * 68 + k * 8 + c];
            a1[2] = eb[(16 + g) * 68 + k * 8 + c + 4]; a1[3] = eb[(24 + g) * 68 + k * 8 + c + 4];
            #pragma unroll
            for (int ni = 0; ni < 4; ni++) {
                const int wi = (((h * 4 + ni) * 8 + k) * 32 + lane) * 2;
                uint2 bq = __ldg((const uint2*)&g_wfq[wi]);
                uint2 bk = __ldg((const uint2*)&g_wfk[wi]);
                mma_tf32(Dq[0][ni], a0, (const unsigned*)&bq);
                mma_tf32(Dq[1][ni], a1, (const unsigned*)&bq);
                mma_tf32(Dk[0][ni], a0, (const unsigned*)&bk);
                mma_tf32(Dk[1][ni], a1, (const unsigned*)&bk);
            }
        }

        // combine: qk[j] = sum_d (EQ+qc)(EK+kc)
        float acc[4] = {0.f, 0.f, 0.f, 0.f};
        #pragma unroll
        for (int mi = 0; mi < 2; mi++) {
            int r0 = mi * 16 + g;
            #pragma unroll
            for (int ni = 0; ni < 4; ni++) {
                int ch = h * 32 + ni * 8 + 2 * c;
                float q0 = sQC[ch], q1 = sQC[ch + 1];
                float2 kA = __ldg((const float2*)(g_kc + (size_t)(bN + jg0 + r0) * NDIM + ch));
                float2 kB = __ldg((const float2*)(g_kc + (size_t)(bN + jg0 + r0 + 8) * NDIM + ch));
                acc[mi * 2]     += (Dq[mi][ni][0] + q0) * (Dk[mi][ni][0] + kA.x)
                                 + (Dq[mi][ni][1] + q1) * (Dk[mi][ni][1] + kA.y);
                acc[mi * 2 + 1] += (Dq[mi][ni][2] + q0) * (Dk[mi][ni][2] + kB.x)
                                 + (Dq[mi][ni][3] + q1) * (Dk[mi][ni][3] + kB.y);
            }
        }
        #pragma unroll
        for (int t = 1; t <= 2; t <<= 1) {
            acc[0] += __shfl_xor_sync(0xffffffffu, acc[0], t);
            acc[1] += __shfl_xor_sync(0xffffffffu, acc[1], t);
            acc[2] += __shfl_xor_sync(0xffffffffu, acc[2], t);
            acc[3] += __shfl_xor_sync(0xffffffffu, acc[3], t);
        }
        if (c == 0) {
            sQK[h * 516 + jg0 + g]      = acc[0] * SCALE_F;
            sQK[h * 516 + jg0 + g + 8]  = acc[1] * SCALE_F;
            sQK[h * 516 + jg0 + 16 + g] = acc[2] * SCALE_F;
            sQK[h * 516 + jg0 + 24 + g] = acc[3] * SCALE_F;
        }
    }
    __syncthreads();

    // ---------------- Softmax: one warp owns head h's full row ----------------
    float* srow = sQK + h * 516;
    {
        float m = -1e30f;
        for (int jj = lane; jj < 512; jj += 32) m = fmaxf(m, srow[jj]);
        #pragma unroll
        for (int off = 16; off > 0; off >>= 1) m = fmaxf(m, __shfl_xor_sync(0xffffffffu, m, off));
        float ssum = 0.f;
        float* gatt = g_att + ((size_t)(b * HEADS + h) * N_SZ + i) * N_SZ;
        for (int jj = lane; jj < 512; jj += 32) {
            float p = __expf(srow[jj] - m);
            float pr = __uint_as_float(f2tf(p));  // tf32-representable: exact in mma
            srow[jj] = pr;
            gatt[jj] = pr;
            ssum += pr;
        }
        #pragma unroll
        for (int off = 16; off > 0; off >>= 1) ssum += __shfl_xor_sync(0xffffffffu, ssum, off);
        if (lane == 0) g_ssum[(size_t)(bN + i) * HEADS + h] = ssum;
    }

    // ---------------- Phase 2: ctx_e = att @ E via mma ---------------------------
    const int nt = h;            // warp = 8-col d-slice
    float Dc[4] = {0.f, 0.f, 0.f, 0.f};

    for (int pass = 0; pass < 2; pass++) {
        __syncthreads();
        {   // stage 256 x 64 edge rows (stride 68): 16 float4/thread
            const float4* src = (const float4*)(edgeRowBase + (size_t)pass * 256 * EDIM);
            #pragma unroll
            for (int u = 0; u < 16; u++) {
                int idx = tid + u * 256;
                int row = idx >> 4, q = idx & 15;
                cp_async16(sE + row * 68 + q * 4, src + idx);
            }
            asm volatile("cp.async.commit_group;");
            asm volatile("cp.async.wait_group 0;");
        }
        __syncthreads();

        #pragma unroll
        for (int cc = 0; cc < 32; cc++) {
            const int jl = cc * 8;
            const int jg = pass * 256 + jl;
            unsigned aa[4], bb[2];
            aa[0] = (g < 8) ? __float_as_uint(sQK[g * 516 + jg + c]) : 0u;
            aa[1] = 0u;
            aa[2] = (g < 8) ? __float_as_uint(sQK[g * 516 + jg + c + 4]) : 0u;
            aa[3] = 0u;
            bb[0] = __float_as_uint(sE[(jl + c) * 68 + nt * 8 + g]);
            bb[1] = __float_as_uint(sE[(jl + c + 4) * 68 + nt * 8 + g]);
            mma_tf32(Dc, aa, bb);
        }
    }
    // lane (g,c) holds head g's ctx_e at cols nt*8 + {2c, 2c+1}
    if (g < 8) {
        sCE[g * 64 + nt * 8 + 2 * c]     = Dc[0];
        sCE[g * 64 + nt * 8 + 2 * c + 1] = Dc[1];
    }
    __syncthreads();
    g_ce[(size_t)(bN + i) * 512 + tid]       = sCE[tid];
    g_ce[(size_t)(bN + i) * 512 + 256 + tid] = sCE[256 + tid];
}

// =================================================================================
// Kernel C: out = ( Wev·ctx_e + att@vc ) / ssum.  CTA = (it, h, b), 256 threads.
// =================================================================================
__global__ __launch_bounds__(256) void out_kernel(
    const float* __restrict__ Wev,
    float* __restrict__ out)
{
    extern __shared__ float smC[];
    float* svc  = smC;               // 512 x 32
    float* sWev = smC + 16384;       // 32 x 65
    float* sCe  = smC + 18464;       // 64 x 64
    // total 22560 floats

    const int it = blockIdx.x;
    const int h  = blockIdx.y;
    const int b  = blockIdx.z;
    const int tid = threadIdx.x;
    const int ti = tid >> 5;
    const int lane = tid & 31;

    for (int idx = tid; idx < 512 * 8; idx += 256) {
        int j = idx >> 3, q = idx & 7;
        float4 v = __ldg((const float4*)&g_vc[(size_t)(b * N_SZ + j) * NDIM + h * 32 + q * 4]);
        *(float4*)&svc[j * 32 + q * 4] = v;
    }
    for (int idx = tid; idx < 2048; idx += 256) {
        int row = idx >> 6, dp = idx & 63;
        sWev[row * 65 + dp] = __ldg(&Wev[(h * 32 + row) * 64 + dp]);
    }
    for (int idx = tid; idx < 64 * 16; idx += 256) {
        int il = idx >> 4, q = idx & 15;
        float4 v = __ldg((const float4*)&g_ce[(size_t)(b * N_SZ + it * 64 + il) * 512 + h * 64 + q * 4]);
        *(float4*)&sCe[il * 64 + q * 4] = v;
    }
    __syncthreads();

    for (int iq = 0; iq < 2; iq++) {
        const int i0 = iq * 32 + ti * 4;
        const float* arow = g_att + ((size_t)(b * HEADS + h) * N_SZ + it * 64 + i0) * N_SZ;
        float acc0 = 0.f, acc1 = 0.f, acc2 = 0.f, acc3 = 0.f;
        #pragma unroll 4
        for (int j = 0; j < 512; j += 4) {
            float4 a0 = __ldg((const float4*)(arow + j));
            float4 a1 = __ldg((const float4*)(arow + 512 + j));
            float4 a2 = __ldg((const float4*)(arow + 1024 + j));
            float4 a3 = __ldg((const float4*)(arow + 1536 + j));
            float v0 = svc[(j + 0) * 32 + lane];
            float v1 = svc[(j + 1) * 32 + lane];
            float v2 = svc[(j + 2) * 32 + lane];
            float v3 = svc[(j + 3) * 32 + lane];
            acc0 += a0.x * v0 + a0.y * v1 + a0.z * v2 + a0.w * v3;
            acc1 += a1.x * v0 + a1.y * v1 + a1.z * v2 + a1.w * v3;
            acc2 += a2.x * v0 + a2.y * v1 + a2.z * v2 + a2.w * v3;
            acc3 += a3.x * v0 + a3.y * v1 + a3.z * v2 + a3.w * v3;
        }
        float accs[4] = {acc0, acc1, acc2, acc3};
        #pragma unroll
        for (int ii = 0; ii < 4; ii++) {
            int il = i0 + ii;
            float dot = 0.f;
            #pragma unroll 8
            for (int dp = 0; dp < 64; dp++)
                dot += sCe[il * 64 + dp] * sWev[lane * 65 + dp];
            int ig = it * 64 + il;
            float inv = 1.f / __ldg(&g_ssum[(size_t)(b * N_SZ + ig) * HEADS + h]);
            out[(size_t)(b * N_SZ + ig) * NDIM + h * 32 + lane] = (dot + accs[ii]) * inv;
        }
    }
}

// =================================================================================
extern "C" void kernel_launch(void* const* d_in, const int* in_sizes, int n_in,
                              void* d_out, int out_size)
{
    const float* node = (const float*)d_in[0];
    const float* edge = (const float*)d_in[1];
    const float* Wnq  = (const float*)d_in[2];
    const float* bnq  = (const float*)d_in[3];
    const float* Wnk  = (const float*)d_in[4];
    const float* bnk  = (const float*)d_in[5];
    const float* Wnv  = (const float*)d_in[6];
    const float* bnv  = (const float*)d_in[7];
    const float* Weq  = (const float*)d_in[8];
    const float* beq  = (const float*)d_in[9];
    const float* Wek  = (const float*)d_in[10];
    const float* bek  = (const float*)d_in[11];
    const float* Wev  = (const float*)d_in[12];
    const float* bev  = (const float*)d_in[13];
    float* out = (float*)d_out;

    const int smemA = (16 * 257 + 64 * 260) * 4;     // 83008 B
    const int smemB = 22304 * 4;                     // 89216 B
    const int smemC = 22560 * 4;                     // 90240 B
    cudaFuncSetAttribute(node_proj_kernel, cudaFuncAttributeMaxDynamicSharedMemorySize, smemA);
    cudaFuncSetAttribute(attn_kernel, cudaFuncAttributeMaxDynamicSharedMemorySize, smemB);
    cudaFuncSetAttribute(out_kernel, cudaFuncAttributeMaxDynamicSharedMemorySize, smemC);

    weight_frag_kernel<<<32, 256>>>(Weq, Wek);

    dim3 gridA(64, 3);
    node_proj_kernel<<<gridA, 256, smemA>>>(node, Wnq, bnq, Wnk, bnk, Wnv, bnv, beq, bek, bev);

    dim3 gridB(N_SZ, B_SZ);
    attn_kernel<<<gridB, 256, smemB>>>(edge);

    dim3 gridC(8, HEADS, B_SZ);
    out_kernel<<<gridC, 256, smemC>>>(Wev, out);
}

// round 8
// speedup vs baseline: 1.4926x; 1.2504x over previous
#include <cuda_runtime.h>
#include <cuda_fp16.h>
#include <math.h>

#define B_SZ 2
#define N_SZ 512
#define EDIM 64
#define NDIM 256
#define HEADS 8
#define DH 32
#define SCALE_F 0.17677669529663687f  // 1/sqrt(32)

// ---------------- scratch (device globals; no allocation allowed) ----------------
__device__ float g_qc[B_SZ * N_SZ * NDIM];   // nq + beq
__device__ float g_kc[B_SZ * N_SZ * NDIM];   // nk + bek
__device__ float g_vc[B_SZ * N_SZ * NDIM];   // nv + bev
__device__ float g_att[B_SZ * HEADS * N_SZ * N_SZ];  // unnormalized softmax (16MB)
__device__ float g_ce[B_SZ * N_SZ * HEADS * EDIM];   // ctx_e per (b,i,h,64)
__device__ float g_ssum[B_SZ * N_SZ * HEADS];        // softmax denominators
__device__ uint2 g_wfq16[4096];  // fp16 fragment-ordered Weq [h][ni][ks][lane]
__device__ uint2 g_wfk16[4096];  // fp16 fragment-ordered Wek
__device__ float g_po[B_SZ * HEADS * 4 * N_SZ * DH]; // att@vc partials [b][h][jq][i][d]

// ---------------- helpers ----------------
__device__ __forceinline__ unsigned f2tf(float f) {
    unsigned u; asm("cvt.rna.tf32.f32 %0, %1;" : "=r"(u) : "f"(f)); return u;
}
__device__ __forceinline__ unsigned pack_h2(float x, float y) {
    __half2 h = __floats2half2_rn(x, y);
    return *(unsigned*)&h;
}
__device__ __forceinline__ void mma_tf32(float* d, const unsigned* a, const unsigned* b) {
    asm("mma.sync.aligned.m16n8k8.row.col.f32.tf32.tf32.f32 "
        "{%0,%1,%2,%3}, {%4,%5,%6,%7}, {%8,%9}, {%0,%1,%2,%3};"
        : "+f"(d[0]), "+f"(d[1]), "+f"(d[2]), "+f"(d[3])
        : "r"(a[0]), "r"(a[1]), "r"(a[2]), "r"(a[3]), "r"(b[0]), "r"(b[1]));
}
__device__ __forceinline__ void mma_f16(float* d, const unsigned* a, const unsigned* b) {
    asm("mma.sync.aligned.m16n8k16.row.col.f32.f16.f16.f32 "
        "{%0,%1,%2,%3}, {%4,%5,%6,%7}, {%8,%9}, {%0,%1,%2,%3};"
        : "+f"(d[0]), "+f"(d[1]), "+f"(d[2]), "+f"(d[3])
        : "r"(a[0]), "r"(a[1]), "r"(a[2]), "r"(a[3]), "r"(b[0]), "r"(b[1]));
}
__device__ __forceinline__ void cp_async16(void* smem_dst, const void* gsrc) {
    unsigned s = (unsigned)__cvta_generic_to_shared(smem_dst);
    asm volatile("cp.async.cg.shared.global [%0], [%1], 16;" :: "r"(s), "l"(gsrc));
}

// =================================================================================
// Kernel W: build fp16 fragment-ordered weight tables.
// idx = ((h*4+ni)*4+ks)*32 + lane
// =================================================================================
__global__ __launch_bounds__(256) void weight_frag_kernel(
    const float* __restrict__ Weq, const float* __restrict__ Wek)
{
    int idx = blockIdx.x * 256 + threadIdx.x;   // 0..4095
    if (idx >= 4096) return;
    int l  = idx & 31;
    int ks = (idx >> 5) & 3;
    int ni = (idx >> 7) & 3;
    int hh = idx >> 9;
    int gg = l >> 2, cc = l & 3;
    int wrow = hh * 32 + ni * 8 + gg;
    const float* wq = Weq + wrow * 64 + ks * 16;
    const float* wk = Wek + wrow * 64 + ks * 16;
    g_wfq16[idx] = make_uint2(pack_h2(wq[2*cc], wq[2*cc+1]), pack_h2(wq[2*cc+8], wq[2*cc+9]));
    g_wfk16[idx] = make_uint2(pack_h2(wk[2*cc], wk[2*cc+1]), pack_h2(wk[2*cc+8], wk[2*cc+9]));
}

// =================================================================================
// Kernel A: node projections. grid (64, 3), 16 rows/CTA.
// =================================================================================
__global__ __launch_bounds__(256) void node_proj_kernel(
    const float* __restrict__ node,
    const float* __restrict__ Wnq, const float* __restrict__ bnq,
    const float* __restrict__ Wnk, const float* __restrict__ bnk,
    const float* __restrict__ Wnv, const float* __restrict__ bnv,
    const float* __restrict__ beq, const float* __restrict__ bek,
    const float* __restrict__ bev)
{
    extern __shared__ float smA[];
    float* node_s = smA;              // 16*257
    float* wt     = smA + 16 * 257;   // 64*260

    const int tid = threadIdx.x;
    const int r  = tid & 15;
    const int cg = tid >> 4;
    const int r0 = blockIdx.x * 16;
    const int p  = blockIdx.y;

    const float* W  = (p == 0) ? Wnq : (p == 1) ? Wnk : Wnv;
    const float* b1 = (p == 0) ? bnq : (p == 1) ? bnk : bnv;
    const float* b2 = (p == 0) ? beq : (p == 1) ? bek : bev;
    float* dst = (p == 0) ? g_qc : (p == 1) ? g_kc : g_vc;

    for (int idx = tid; idx < 16 * 256; idx += 256) {
        int rr = idx >> 8, k = idx & 255;
        node_s[rr * 257 + k] = node[(r0 + rr) * 256 + k];
    }

    float acc[16];
    #pragma unroll
    for (int q = 0; q < 16; q++) acc[q] = 0.f;

    for (int kt = 0; kt < 4; kt++) {
        __syncthreads();
        for (int idx = tid; idx < 64 * 256; idx += 256) {
            int c = idx >> 6, kk = idx & 63;
            wt[kk * 260 + c] = W[c * 256 + kt * 64 + kk];
        }
        __syncthreads();
        #pragma unroll 4
        for (int kk = 0; kk < 64; kk++) {
            float nv = node_s[r * 257 + kt * 64 + kk];
            const float* wrow = &wt[kk * 260 + cg * 16];
            float4 w0 = *(const float4*)(wrow);
            float4 w1 = *(const float4*)(wrow + 4);
            float4 w2 = *(const float4*)(wrow + 8);
            float4 w3 = *(const float4*)(wrow + 12);
            acc[0]  += w0.x * nv; acc[1]  += w0.y * nv; acc[2]  += w0.z * nv; acc[3]  += w0.w * nv;
            acc[4]  += w1.x * nv; acc[5]  += w1.y * nv; acc[6]  += w1.z * nv; acc[7]  += w1.w * nv;
            acc[8]  += w2.x * nv; acc[9]  += w2.y * nv; acc[10] += w2.z * nv; acc[11] += w2.w * nv;
            acc[12] += w3.x * nv; acc[13] += w3.y * nv; acc[14] += w3.z * nv; acc[15] += w3.w * nv;
        }
    }
    int row = r0 + r;
    #pragma unroll
    for (int q4 = 0; q4 < 4; q4++) {
        float4 bb1 = *(const float4*)&b1[cg * 16 + q4 * 4];
        float4 bb2 = *(const float4*)&b2[cg * 16 + q4 * 4];
        float4 v;
        v.x = acc[q4 * 4 + 0] + bb1.x + bb2.x;
        v.y = acc[q4 * 4 + 1] + bb1.y + bb2.y;
        v.z = acc[q4 * 4 + 2] + bb1.z + bb2.z;
        v.w = acc[q4 * 4 + 3] + bb1.w + bb2.w;
        *(float4*)&dst[row * 256 + cg * 16 + q4 * 4] = v;
    }
}

// =================================================================================
// Kernel B: per (b,i) CTA, 256 threads = 8 warps (warp = head), 2 CTAs/SM.
// Phase 1: fp16 mma m16n8k16 (2x tensor rate vs tf32); E fp32 in smem, packed to
// half2 at fragment build; weights from L1-resident fp16 fragment tables.
// =================================================================================
__global__ __launch_bounds__(256, 2) void attn_kernel(
    const float* __restrict__ edge)
{
    extern __shared__ float sm[];
    float* sQK = sm;             // 8 x 516 = 4128
    float* sQC = sm + 4128;      // 256
    float* sCE = sm + 4384;      // 512
    float* sE  = sm + 4896;      // phase1: 3 x 2176 ring; phase2: 256 x 68 = 17408
    // total 22304 floats = 89216 bytes

    const int i = blockIdx.x;
    const int b = blockIdx.y;
    const int tid = threadIdx.x;
    const int lane = tid & 31;
    const int h = tid >> 5;      // warp = head
    const int g = lane >> 2;
    const int c = lane & 3;

    const int bN = b * N_SZ;
    const float* edgeRowBase = edge + (size_t)(bN + i) * N_SZ * EDIM;

    // ---- start cp.async of tile 0 ----
    {
        const float4* src = (const float4*)(edgeRowBase);
        #pragma unroll
        for (int u = 0; u < 2; u++) {
            int idx = tid + u * 256;
            int row = idx >> 4, q = idx & 15;
            cp_async16(sE + row * 68 + q * 4, src + idx);
        }
        asm volatile("cp.async.commit_group;");
    }
    sQC[tid] = g_qc[(bN + i) * NDIM + tid];

    // ---------------- Phase 1: 16 tiles of 32 j, fp16 mma ----------------
    for (int jt = 0; jt < 16; jt++) {
        if (jt < 15) {
            const float4* src = (const float4*)(edgeRowBase + (jt + 1) * 32 * EDIM);
            float* dstb = sE + ((jt + 1) % 3) * 2176;
            #pragma unroll
            for (int u = 0; u < 2; u++) {
                int idx = tid + u * 256;
                int row = idx >> 4, q = idx & 15;
                cp_async16(dstb + row * 68 + q * 4, src + idx);
            }
            asm volatile("cp.async.commit_group;");
            asm volatile("cp.async.wait_group 1;");
        } else {
            asm volatile("cp.async.wait_group 0;");
        }
        __syncthreads();

        const float* eb = sE + (jt % 3) * 2176;
        const int jg0 = jt * 32;

        float Dq[2][4][4], Dk[2][4][4];
        #pragma unroll
        for (int mi = 0; mi < 2; mi++)
            #pragma unroll
            for (int ni = 0; ni < 4; ni++)
                #pragma unroll
                for (int e = 0; e < 4; e++) { Dq[mi][ni][e] = 0.f; Dk[mi][ni][e] = 0.f; }

        #pragma unroll
        for (int ks = 0; ks < 4; ks++) {
            const int col = ks * 16 + 2 * c;
            unsigned a0[4], a1[4];
            {
                float2 e;
                e = *(const float2*)&eb[g * 68 + col];            a0[0] = pack_h2(e.x, e.y);
                e = *(const float2*)&eb[(g + 8) * 68 + col];      a0[1] = pack_h2(e.x, e.y);
                e = *(const float2*)&eb[g * 68 + col + 8];        a0[2] = pack_h2(e.x, e.y);
                e = *(const float2*)&eb[(g + 8) * 68 + col + 8];  a0[3] = pack_h2(e.x, e.y);
                e = *(const float2*)&eb[(g + 16) * 68 + col];     a1[0] = pack_h2(e.x, e.y);
                e = *(const float2*)&eb[(g + 24) * 68 + col];     a1[1] = pack_h2(e.x, e.y);
                e = *(const float2*)&eb[(g + 16) * 68 + col + 8]; a1[2] = pack_h2(e.x, e.y);
                e = *(const float2*)&eb[(g + 24) * 68 + col + 8]; a1[3] = pack_h2(e.x, e.y);
            }
            #pragma unroll
            for (int ni = 0; ni < 4; ni++) {
                const int wi = ((h * 4 + ni) * 4 + ks) * 32 + lane;
                uint2 bq = __ldg(&g_wfq16[wi]);
                uint2 bk = __ldg(&g_wfk16[wi]);
                mma_f16(Dq[0][ni], a0, (const unsigned*)&bq);
                mma_f16(Dq[1][ni], a1, (const unsigned*)&bq);
                mma_f16(Dk[0][ni], a0, (const unsigned*)&bk);
                mma_f16(Dk[1][ni], a1, (const unsigned*)&bk);
            }
        }

        // combine: qk[j] = sum_d (EQ+qc)(EK+kc)
        float acc[4] = {0.f, 0.f, 0.f, 0.f};
        #pragma unroll
        for (int mi = 0; mi < 2; mi++) {
            int r0 = mi * 16 + g;
            #pragma unroll
            for (int ni = 0; ni < 4; ni++) {
                int ch = h * 32 + ni * 8 + 2 * c;
                float q0 = sQC[ch], q1 = sQC[ch + 1];
                float2 kA = __ldg((const float2*)(g_kc + (size_t)(bN + jg0 + r0) * NDIM + ch));
                float2 kB = __ldg((const float2*)(g_kc + (size_t)(bN + jg0 + r0 + 8) * NDIM + ch));
                acc[mi * 2]     += (Dq[mi][ni][0] + q0) * (Dk[mi][ni][0] + kA.x)
                                 + (Dq[mi][ni][1] + q1) * (Dk[mi][ni][1] + kA.y);
                acc[mi * 2 + 1] += (Dq[mi][ni][2] + q0) * (Dk[mi][ni][2] + kB.x)
                                 + (Dq[mi][ni][3] + q1) * (Dk[mi][ni][3] + kB.y);
            }
        }
        #pragma unroll
        for (int t = 1; t <= 2; t <<= 1) {
            acc[0] += __shfl_xor_sync(0xffffffffu, acc[0], t);
            acc[1] += __shfl_xor_sync(0xffffffffu, acc[1], t);
            acc[2] += __shfl_xor_sync(0xffffffffu, acc[2], t);
            acc[3] += __shfl_xor_sync(0xffffffffu, acc[3], t);
        }
        if (c == 0) {
            sQK[h * 516 + jg0 + g]      = acc[0] * SCALE_F;
            sQK[h * 516 + jg0 + g + 8]  = acc[1] * SCALE_F;
            sQK[h * 516 + jg0 + 16 + g] = acc[2] * SCALE_F;
            sQK[h * 516 + jg0 + 24 + g] = acc[3] * SCALE_F;
        }
    }
    __syncthreads();

    // ---------------- Softmax: one warp owns head h's full row ----------------
    float* srow = sQK + h * 516;
    {
        float m = -1e30f;
        for (int jj = lane; jj < 512; jj += 32) m = fmaxf(m, srow[jj]);
        #pragma unroll
        for (int off = 16; off > 0; off >>= 1) m = fmaxf(m, __shfl_xor_sync(0xffffffffu, m, off));
        float ssum = 0.f;
        float* gatt = g_att + ((size_t)(b * HEADS + h) * N_SZ + i) * N_SZ;
        for (int jj = lane; jj < 512; jj += 32) {
            float p = __expf(srow[jj] - m);
            float pr = __uint_as_float(f2tf(p));  // tf32-representable: exact in mma
            srow[jj] = pr;
            gatt[jj] = pr;
            ssum += pr;
        }
        #pragma unroll
        for (int off = 16; off > 0; off >>= 1) ssum += __shfl_xor_sync(0xffffffffu, ssum, off);
        if (lane == 0) g_ssum[(size_t)(bN + i) * HEADS + h] = ssum;
    }

    // ---------------- Phase 2: ctx_e = att @ E via tf32 mma ----------------------
    const int nt = h;            // warp = 8-col d-slice
    float Dc[4] = {0.f, 0.f, 0.f, 0.f};

    for (int pass = 0; pass < 2; pass++) {
        __syncthreads();
        {
            const float4* src = (const float4*)(edgeRowBase + (size_t)pass * 256 * EDIM);
            #pragma unroll
            for (int u = 0; u < 16; u++) {
                int idx = tid + u * 256;
                int row = idx >> 4, q = idx & 15;
                cp_async16(sE + row * 68 + q * 4, src + idx);
            }
            asm volatile("cp.async.commit_group;");
            asm volatile("cp.async.wait_group 0;");
        }
        __syncthreads();

        #pragma unroll
        for (int cc = 0; cc < 32; cc++) {
            const int jl = cc * 8;
            const int jg = pass * 256 + jl;
            unsigned aa[4], bb[2];
            aa[0] = __float_as_uint(sQK[g * 516 + jg + c]);
            aa[1] = 0u;
            aa[2] = __float_as_uint(sQK[g * 516 + jg + c + 4]);
            aa[3] = 0u;
            bb[0] = __float_as_uint(sE[(jl + c) * 68 + nt * 8 + g]);
            bb[1] = __float_as_uint(sE[(jl + c + 4) * 68 + nt * 8 + g]);
            mma_tf32(Dc, aa, bb);
        }
    }
    sCE[g * 64 + nt * 8 + 2 * c]     = Dc[0];
    sCE[g * 64 + nt * 8 + 2 * c + 1] = Dc[1];
    __syncthreads();
    g_ce[(size_t)(bN + i) * 512 + tid]       = sCE[tid];
    g_ce[(size_t)(bN + i) * 512 + 256 + tid] = sCE[256 + tid];
}

// =================================================================================
// Kernel C1: att@vc partials. grid (32 = jq*8+it, 8, 2), 256 threads, 16KB smem.
// Each CTA: i-tile of 64 (it), j-slice of 128 (jq), head h, batch b.
// =================================================================================
__global__ __launch_bounds__(256) void outp_kernel()
{
    __shared__ float svc[128 * 32];  // 16KB

    const int x  = blockIdx.x;
    const int jq = x >> 3;
    const int it = x & 7;
    const int h  = blockIdx.y;
    const int b  = blockIdx.z;
    const int tid = threadIdx.x;
    const int ti = tid >> 5;
    const int lane = tid & 31;
    const int j0 = jq * 128;

    for (int idx = tid; idx < 128 * 8; idx += 256) {
        int j = idx >> 3, q = idx & 7;
        float4 v = __ldg((const float4*)&g_vc[(size_t)(b * N_SZ + j0 + j) * NDIM + h * 32 + q * 4]);
        *(float4*)&svc[j * 32 + q * 4] = v;
    }
    __syncthreads();

    #pragma unroll
    for (int half = 0; half < 2; half++) {
        const int i0 = it * 64 + ti * 8 + half * 4;
        const float* arow = g_att + ((size_t)(b * HEADS + h) * N_SZ + i0) * N_SZ + j0;
        float acc0 = 0.f, acc1 = 0.f, acc2 = 0.f, acc3 = 0.f;
        #pragma unroll 4
        for (int j = 0; j < 128; j += 4) {
            float4 a0 = __ldg((const float4*)(arow + j));
            float4 a1 = __ldg((const float4*)(arow + 512 + j));
            float4 a2 = __ldg((const float4*)(arow + 1024 + j));
            float4 a3 = __ldg((const float4*)(arow + 1536 + j));
            float v0 = svc[(j + 0) * 32 + lane];
            float v1 = svc[(j + 1) * 32 + lane];
            float v2 = svc[(j + 2) * 32 + lane];
            float v3 = svc[(j + 3) * 32 + lane];
            acc0 += a0.x * v0 + a0.y * v1 + a0.z * v2 + a0.w * v3;
            acc1 += a1.x * v0 + a1.y * v1 + a1.z * v2 + a1.w * v3;
            acc2 += a2.x * v0 + a2.y * v1 + a2.z * v2 + a2.w * v3;
            acc3 += a3.x * v0 + a3.y * v1 + a3.z * v2 + a3.w * v3;
        }
        float* po = g_po + (((size_t)(b * HEADS + h) * 4 + jq) * N_SZ + i0) * DH + lane;
        po[0 * DH] = acc0;
        po[1 * DH] = acc1;
        po[2 * DH] = acc2;
        po[3 * DH] = acc3;
    }
}

// =================================================================================
// Kernel C2: reduce partials + Wev·ctx_e epilogue. grid (8, 8, 2), 256 threads.
// =================================================================================
__global__ __launch_bounds__(256) void outr_kernel(
    const float* __restrict__ Wev,
    float* __restrict__ out)
{
    __shared__ float sWev[32 * 65];  // 8320B
    __shared__ float sCe[64 * 64];   // 16KB

    const int it = blockIdx.x;
    const int h  = blockIdx.y;
    const int b  = blockIdx.z;
    const int tid = threadIdx.x;
    const int ti = tid >> 5;
    const int lane = tid & 31;

    for (int idx = tid; idx < 2048; idx += 256) {
        int row = idx >> 6, dp = idx & 63;
        sWev[row * 65 + dp] = __ldg(&Wev[(h * 32 + row) * 64 + dp]);
    }
    for (int idx = tid; idx < 64 * 16; idx += 256) {
        int il = idx >> 4, q = idx & 15;
        float4 v = __ldg((const float4*)&g_ce[(size_t)(b * N_SZ + it * 64 + il) * 512 + h * 64 + q * 4]);
        *(float4*)&sCe[il * 64 + q * 4] = v;
    }
    __syncthreads();

    #pragma unroll
    for (int ii = 0; ii < 8; ii++) {
        int il = ti * 8 + ii;
        int ig = it * 64 + il;
        float a = 0.f;
        #pragma unroll
        for (int jq = 0; jq < 4; jq++)
            a += __ldg(&g_po[(((size_t)(b * HEADS + h) * 4 + jq) * N_SZ + ig) * DH + lane]);
        float dot = 0.f;
        #pragma unroll 8
        for (int dp = 0; dp < 64; dp++)
            dot += sCe[il * 64 + dp] * sWev[lane * 65 + dp];
        float inv = 1.f / __ldg(&g_ssum[(size_t)(b * N_SZ + ig) * HEADS + h]);
        out[(size_t)(b * N_SZ + ig) * NDIM + h * 32 + lane] = (dot + a) * inv;
    }
}

// =================================================================================
extern "C" void kernel_launch(void* const* d_in, const int* in_sizes, int n_in,
                              void* d_out, int out_size)
{
    const float* node = (const float*)d_in[0];
    const float* edge = (const float*)d_in[1];
    const float* Wnq  = (const float*)d_in[2];
    const float* bnq  = (const float*)d_in[3];
    const float* Wnk  = (const float*)d_in[4];
    const float* bnk  = (const float*)d_in[5];
    const float* Wnv  = (const float*)d_in[6];
    const float* bnv  = (const float*)d_in[7];
    const float* Weq  = (const float*)d_in[8];
    const float* beq  = (const float*)d_in[9];
    const float* Wek  = (const float*)d_in[10];
    const float* bek  = (const float*)d_in[11];
    const float* Wev  = (const float*)d_in[12];
    const float* bev  = (const float*)d_in[13];
    float* out = (float*)d_out;

    const int smemA = (16 * 257 + 64 * 260) * 4;     // 83008 B
    const int smemB = 22304 * 4;                     // 89216 B
    cudaFuncSetAttribute(node_proj_kernel, cudaFuncAttributeMaxDynamicSharedMemorySize, smemA);
    cudaFuncSetAttribute(attn_kernel, cudaFuncAttributeMaxDynamicSharedMemorySize, smemB);

    weight_frag_kernel<<<16, 256>>>(Weq, Wek);

    dim3 gridA(64, 3);
    node_proj_kernel<<<gridA, 256, smemA>>>(node, Wnq, bnq, Wnk, bnk, Wnv, bnv, beq, bek, bev);

    dim3 gridB(N_SZ, B_SZ);
    attn_kernel<<<gridB, 256, smemB>>>(edge);

    dim3 gridC1(32, HEADS, B_SZ);
    outp_kernel<<<gridC1, 256>>>();

    dim3 gridC2(8, HEADS, B_SZ);
    outr_kernel<<<gridC2, 256>>>(Wev, out);
}